// round 15
// baseline (speedup 1.0000x reference)
#include <cuda_runtime.h>
#include <cstdint>

// Fixed shapes from reference setup_inputs
#define BS   32
#define C    256
#define HW   4096          // 64*64
#define HID  32            // C / R
#define NPLANES (BS * C)   // 8192

// Scratch in device globals (no allocations allowed)
__device__ float g_pooled[NPLANES];   // [BS, C] plane means

// ---------------------------------------------------------------------------
// Kernel 1: mean pool over H*W. One CTA per plane, 256 threads, 4 float4
// front-batched loads. (Proven 23.3us / 5.9TB/s geometry — unchanged.)
// ---------------------------------------------------------------------------
__global__ __launch_bounds__(256) void pool_kernel(const float* __restrict__ x) {
    const int p = blockIdx.x;                  // plane = b*C + c
    const int t = threadIdx.x;
    const float4* __restrict__ x4 = reinterpret_cast<const float4*>(x) + (size_t)p * (HW / 4);

    float4 v0 = x4[t];
    float4 v1 = x4[t + 256];
    float4 v2 = x4[t + 512];
    float4 v3 = x4[t + 768];

    float s = ((v0.x + v0.y) + (v0.z + v0.w))
            + ((v1.x + v1.y) + (v1.z + v1.w))
            + ((v2.x + v2.y) + (v2.z + v2.w))
            + ((v3.x + v3.y) + (v3.z + v3.w));

#pragma unroll
    for (int o = 16; o > 0; o >>= 1) s += __shfl_down_sync(0xffffffffu, s, o);

    __shared__ float ws[8];
    if ((t & 31) == 0) ws[t >> 5] = s;
    __syncthreads();
    if (t < 8) {
        float v = ws[t];
#pragma unroll
        for (int o = 4; o > 0; o >>= 1) v += __shfl_down_sync(0xffu, v, o);
        if (t == 0) g_pooled[p] = v * (1.0f / (float)HW);
    }
}

// ---------------------------------------------------------------------------
// Kernel 2 (fused): per-CTA coefficient computation + apply.
// One CTA per plane (R2-proven geometry). The CTA:
//   1. front-batches its 4 x float4 loads (DRAM latency hidden by step 2/3)
//   2. computes h = relu(W1 @ pooled_b + b1)   (warp 0+, w1 via __ldg -> L1)
//   3. computes its channel's 4 logits -> (a0, a1, q0, q1)
//   4. out = max(x*a0+q0, x*a1+q1), __stcs stores.
// ---------------------------------------------------------------------------
__global__ __launch_bounds__(256) void apply_kernel(
    const float* __restrict__ x,
    const float* __restrict__ w1, const float* __restrict__ b1,
    const float* __restrict__ w2, const float* __restrict__ b2,
    float* __restrict__ out)
{
    const int p = (NPLANES - 1) - blockIdx.x;   // reverse traversal
    const int b = p >> 8;
    const int c = p & 255;
    const int t = threadIdx.x;

    const float4* __restrict__ x4 = reinterpret_cast<const float4*>(x) + (size_t)p * (HW / 4);
    float4* __restrict__ o4       = reinterpret_cast<float4*>(out)     + (size_t)p * (HW / 4);

    // ---- 1. Issue the big streaming loads FIRST (latency hidden below) ----
    float4 v0 = __ldcs(&x4[t]);
    float4 v1 = __ldcs(&x4[t + 256]);
    float4 v2 = __ldcs(&x4[t + 512]);
    float4 v3 = __ldcs(&x4[t + 768]);

    // ---- 2. Hidden layer: h = relu(w1 @ pooled_b + b1) ----
    __shared__ float sp[C];
    __shared__ float sh[HID];
    __shared__ float sz[4];

    sp[t] = __ldg(&g_pooled[b * C + t]);        // 1KB, L2-hot
    __syncthreads();

    if (t < HID) {
        float acc = __ldg(&b1[t]);
        const float* __restrict__ w1r = w1 + t * C;
#pragma unroll 8
        for (int i = 0; i < C; ++i) acc = fmaf(sp[i], __ldg(&w1r[i]), acc);
        sh[t] = fmaxf(acc, 0.f);
    }
    __syncthreads();

    // ---- 3. This CTA's 4 logits: rows {2c, 2c+1, 512+2c, 512+2c+1} of w2 ----
    if (t < 4) {
        const int ro = (t < 2) ? (2 * c + t) : (512 + 2 * c + (t - 2));
        const float* __restrict__ w2r = w2 + (size_t)ro * HID;
        float z = __ldg(&b2[ro]);
#pragma unroll
        for (int h = 0; h < HID; ++h) z = fmaf(sh[h], __ldg(&w2r[h]), z);
        sz[t] = tanhf(0.5f * z);                // == 2*sigmoid(z) - 1
    }
    __syncthreads();

    const float a0 = 1.0f + sz[0];              // init 1, lambda_alpha 1.0
    const float q0 = 1.0f + 0.5f * sz[1];       // init 1, lambda_beta  0.5
    const float a1 = sz[2];                     // init 0
    const float q1 = 0.5f * sz[3];              // init 0

    // ---- 4. Apply + streaming stores ----
    float4 r0, r1, r2, r3;
    r0.x = fmaxf(fmaf(v0.x, a0, q0), fmaf(v0.x, a1, q1));
    r0.y = fmaxf(fmaf(v0.y, a0, q0), fmaf(v0.y, a1, q1));
    r0.z = fmaxf(fmaf(v0.z, a0, q0), fmaf(v0.z, a1, q1));
    r0.w = fmaxf(fmaf(v0.w, a0, q0), fmaf(v0.w, a1, q1));
    r1.x = fmaxf(fmaf(v1.x, a0, q0), fmaf(v1.x, a1, q1));
    r1.y = fmaxf(fmaf(v1.y, a0, q0), fmaf(v1.y, a1, q1));
    r1.z = fmaxf(fmaf(v1.z, a0, q0), fmaf(v1.z, a1, q1));
    r1.w = fmaxf(fmaf(v1.w, a0, q0), fmaf(v1.w, a1, q1));
    r2.x = fmaxf(fmaf(v2.x, a0, q0), fmaf(v2.x, a1, q1));
    r2.y = fmaxf(fmaf(v2.y, a0, q0), fmaf(v2.y, a1, q1));
    r2.z = fmaxf(fmaf(v2.z, a0, q0), fmaf(v2.z, a1, q1));
    r2.w = fmaxf(fmaf(v2.w, a0, q0), fmaf(v2.w, a1, q1));
    r3.x = fmaxf(fmaf(v3.x, a0, q0), fmaf(v3.x, a1, q1));
    r3.y = fmaxf(fmaf(v3.y, a0, q0), fmaf(v3.y, a1, q1));
    r3.z = fmaxf(fmaf(v3.z, a0, q0), fmaf(v3.z, a1, q1));
    r3.w = fmaxf(fmaf(v3.w, a0, q0), fmaf(v3.w, a1, q1));

    __stcs(&o4[t],       r0);
    __stcs(&o4[t + 256], r1);
    __stcs(&o4[t + 512], r2);
    __stcs(&o4[t + 768], r3);
}

extern "C" void kernel_launch(void* const* d_in, const int* in_sizes, int n_in,
                              void* d_out, int out_size) {
    const float* x  = (const float*)d_in[0];
    const float* w1 = (const float*)d_in[1];
    const float* b1 = (const float*)d_in[2];
    const float* w2 = (const float*)d_in[3];
    const float* b2 = (const float*)d_in[4];
    float* out = (float*)d_out;

    pool_kernel <<<NPLANES, 256>>>(x);
    apply_kernel<<<NPLANES, 256>>>(x, w1, b1, w2, b2, out);
}

// round 16
// speedup vs baseline: 3.3729x; 3.3729x over previous
#include <cuda_runtime.h>
#include <cstdint>

// Fixed shapes from reference setup_inputs
#define BS   32
#define C    256
#define HW   4096          // 64*64
#define HID  32            // C / R
#define NPLANES (BS * C)   // 8192

// Scratch in device globals (no allocations allowed)
__device__ float  g_pooled[NPLANES];   // [BS, C] plane means
__device__ float4 g_coef[NPLANES];     // (a0, a1, q0, q1) per (b,c)

// --- 32-byte (256-bit) global loads: LDG.256 on sm_103a ---
__device__ __forceinline__ void ld_32B(const void* p, float4& a, float4& b) {
    unsigned long long r0, r1, r2, r3;
    asm volatile("ld.global.v4.b64 {%0,%1,%2,%3}, [%4];"
                 : "=l"(r0), "=l"(r1), "=l"(r2), "=l"(r3) : "l"(p));
    a.x = __uint_as_float((unsigned)r0);  a.y = __uint_as_float((unsigned)(r0 >> 32));
    a.z = __uint_as_float((unsigned)r1);  a.w = __uint_as_float((unsigned)(r1 >> 32));
    b.x = __uint_as_float((unsigned)r2);  b.y = __uint_as_float((unsigned)(r2 >> 32));
    b.z = __uint_as_float((unsigned)r3);  b.w = __uint_as_float((unsigned)(r3 >> 32));
}
// Streaming (evict-first) 32B load for single-use data
__device__ __forceinline__ void ld_32B_cs(const void* p, float4& a, float4& b) {
    unsigned long long r0, r1, r2, r3;
    asm volatile("ld.global.cs.v4.b64 {%0,%1,%2,%3}, [%4];"
                 : "=l"(r0), "=l"(r1), "=l"(r2), "=l"(r3) : "l"(p));
    a.x = __uint_as_float((unsigned)r0);  a.y = __uint_as_float((unsigned)(r0 >> 32));
    a.z = __uint_as_float((unsigned)r1);  a.w = __uint_as_float((unsigned)(r1 >> 32));
    b.x = __uint_as_float((unsigned)r2);  b.y = __uint_as_float((unsigned)(r2 >> 32));
    b.z = __uint_as_float((unsigned)r3);  b.w = __uint_as_float((unsigned)(r3 >> 32));
}

// ---------------------------------------------------------------------------
// Kernel 1: mean pool over H*W. One CTA per plane, 256 threads.
// 2 x 32B loads per thread (same 64B/thread as proven geometry, half the LDGs).
// ---------------------------------------------------------------------------
__global__ __launch_bounds__(256) void pool_kernel(const float* __restrict__ x) {
    const int p = blockIdx.x;                  // plane = b*C + c
    const int t = threadIdx.x;
    const char* base = reinterpret_cast<const char*>(x) + (size_t)p * (HW * 4);

    float4 v0, v1, v2, v3;
    ld_32B(base + t * 32,        v0, v1);      // bytes [0, 8192)
    ld_32B(base + 8192 + t * 32, v2, v3);      // bytes [8192, 16384)

    float s = ((v0.x + v0.y) + (v0.z + v0.w))
            + ((v1.x + v1.y) + (v1.z + v1.w))
            + ((v2.x + v2.y) + (v2.z + v2.w))
            + ((v3.x + v3.y) + (v3.z + v3.w));

#pragma unroll
    for (int o = 16; o > 0; o >>= 1) s += __shfl_down_sync(0xffffffffu, s, o);

    __shared__ float ws[8];
    if ((t & 31) == 0) ws[t >> 5] = s;
    __syncthreads();
    if (t < 8) {
        float v = ws[t];
#pragma unroll
        for (int o = 4; o > 0; o >>= 1) v += __shfl_down_sync(0xffu, v, o);
        if (t == 0) g_pooled[p] = v * (1.0f / (float)HW);
    }
}

// ---------------------------------------------------------------------------
// Kernel 2: coefficients. One CTA per batch element (32 CTAs, 256 threads).
// (Unchanged proven code.)
// ---------------------------------------------------------------------------
__global__ __launch_bounds__(256) void coef_kernel(const float* __restrict__ w1,
                                                   const float* __restrict__ b1,
                                                   const float* __restrict__ w2,
                                                   const float* __restrict__ b2) {
    const int b = blockIdx.x;
    const int t = threadIdx.x;

    __shared__ float sp[C];
    __shared__ float sh[HID];

    sp[t] = g_pooled[b * C + t];
    __syncthreads();

    if (t < HID) {
        float acc = b1[t];
        const float* __restrict__ w1r = w1 + t * C;
#pragma unroll 8
        for (int i = 0; i < C; ++i) acc = fmaf(sp[i], w1r[i], acc);
        sh[t] = fmaxf(acc, 0.f);
    }
    __syncthreads();

    const int cc = t;
    float z00 = b2[2 * cc];               // k=0 alpha
    float z01 = b2[2 * cc + 1];           // k=0 beta
    float z10 = b2[512 + 2 * cc];         // k=1 alpha
    float z11 = b2[512 + 2 * cc + 1];     // k=1 beta
    const float* __restrict__ r00 = w2 + (size_t)(2 * cc) * HID;
    const float* __restrict__ r01 = w2 + (size_t)(2 * cc + 1) * HID;
    const float* __restrict__ r10 = w2 + (size_t)(512 + 2 * cc) * HID;
    const float* __restrict__ r11 = w2 + (size_t)(512 + 2 * cc + 1) * HID;
#pragma unroll
    for (int h = 0; h < HID; ++h) {
        const float hv = sh[h];
        z00 = fmaf(hv, r00[h], z00);
        z01 = fmaf(hv, r01[h], z01);
        z10 = fmaf(hv, r10[h], z10);
        z11 = fmaf(hv, r11[h], z11);
    }
    float4 cf;
    cf.x = 1.0f + tanhf(0.5f * z00);          // a0 = 1 + 1.0*delta
    cf.y =        tanhf(0.5f * z10);          // a1 = 0 + 1.0*delta
    cf.z = 1.0f + 0.5f * tanhf(0.5f * z01);   // q0 = 1 + 0.5*delta
    cf.w =        0.5f * tanhf(0.5f * z11);   // q1 = 0 + 0.5*delta
    g_coef[b * C + cc] = cf;
}

// ---------------------------------------------------------------------------
// Kernel 3: out = max(x*a0+q0, x*a1+q1). One plane per CTA, 256 threads,
// reverse order (R2-proven). Reads: 2 x 32B streaming loads per thread.
// Stores: 4 x 16B __stcs (mirrors the 32B load layout).
// ---------------------------------------------------------------------------
__global__ __launch_bounds__(256) void apply_kernel(const float* __restrict__ x,
                                                    float* __restrict__ out) {
    const int p = (NPLANES - 1) - blockIdx.x;   // reverse traversal
    const int t = threadIdx.x;

    const float4 cf = __ldcg(&g_coef[p]);
    const float a0 = cf.x, a1 = cf.y, q0 = cf.z, q1 = cf.w;

    const char* base = reinterpret_cast<const char*>(x) + (size_t)p * (HW * 4);
    float4* __restrict__ o4 = reinterpret_cast<float4*>(out) + (size_t)p * (HW / 4);

    float4 v0, v1, v2, v3;
    ld_32B_cs(base + t * 32,        v0, v1);
    ld_32B_cs(base + 8192 + t * 32, v2, v3);

#define APPLY4(r, v)                                                         \
    r.x = fmaxf(fmaf(v.x, a0, q0), fmaf(v.x, a1, q1));                       \
    r.y = fmaxf(fmaf(v.y, a0, q0), fmaf(v.y, a1, q1));                       \
    r.z = fmaxf(fmaf(v.z, a0, q0), fmaf(v.z, a1, q1));                       \
    r.w = fmaxf(fmaf(v.w, a0, q0), fmaf(v.w, a1, q1));

    float4 r0, r1, r2, r3;
    APPLY4(r0, v0) APPLY4(r1, v1) APPLY4(r2, v2) APPLY4(r3, v3)
#undef APPLY4

    // Mirror the 32B-load layout: v0/v1 -> [t*32, +32); v2/v3 -> [8192+t*32, +32)
    __stcs(&o4[2 * t],           r0);
    __stcs(&o4[2 * t + 1],       r1);
    __stcs(&o4[512 + 2 * t],     r2);
    __stcs(&o4[512 + 2 * t + 1], r3);
}

extern "C" void kernel_launch(void* const* d_in, const int* in_sizes, int n_in,
                              void* d_out, int out_size) {
    const float* x  = (const float*)d_in[0];
    const float* w1 = (const float*)d_in[1];
    const float* b1 = (const float*)d_in[2];
    const float* w2 = (const float*)d_in[3];
    const float* b2 = (const float*)d_in[4];
    float* out = (float*)d_out;

    pool_kernel <<<NPLANES, 256>>>(x);
    coef_kernel <<<BS,      256>>>(w1, b1, w2, b2);
    apply_kernel<<<NPLANES, 256>>>(x, out);
}

// round 17
// speedup vs baseline: 3.6015x; 1.0678x over previous
#include <cuda_runtime.h>
#include <cstdint>

// Fixed shapes from reference setup_inputs
#define BS   32
#define C    256
#define HW   4096          // 64*64
#define HID  32            // C / R
#define NPLANES (BS * C)   // 8192

// Scratch in device globals (no allocations allowed)
__device__ float  g_pooled[NPLANES];   // [BS, C] plane means
__device__ float4 g_coef[NPLANES];     // packed (a0, a1, q0, q1) per (b,c)

// ---------------------------------------------------------------------------
// Kernel 1: mean pool over H*W. One CTA per plane, 256 threads, 4 float4
// front-batched loads (MLP=4). Warp-shuffle + smem reduce.
// Measured 23.3us / 5.9TB/s — at the streaming-read ceiling.
// ---------------------------------------------------------------------------
__global__ __launch_bounds__(256) void pool_kernel(const float* __restrict__ x) {
    const int p = blockIdx.x;                  // plane = b*C + c
    const int t = threadIdx.x;
    const float4* __restrict__ x4 = reinterpret_cast<const float4*>(x) + (size_t)p * (HW / 4);

    float4 v0 = x4[t];
    float4 v1 = x4[t + 256];
    float4 v2 = x4[t + 512];
    float4 v3 = x4[t + 768];

    float s = ((v0.x + v0.y) + (v0.z + v0.w))
            + ((v1.x + v1.y) + (v1.z + v1.w))
            + ((v2.x + v2.y) + (v2.z + v2.w))
            + ((v3.x + v3.y) + (v3.z + v3.w));

#pragma unroll
    for (int o = 16; o > 0; o >>= 1) s += __shfl_down_sync(0xffffffffu, s, o);

    __shared__ float ws[8];
    if ((t & 31) == 0) ws[t >> 5] = s;
    __syncthreads();
    if (t < 8) {
        float v = ws[t];
#pragma unroll
        for (int o = 4; o > 0; o >>= 1) v += __shfl_down_sync(0xffu, v, o);
        if (t == 0) g_pooled[p] = v * (1.0f / (float)HW);
    }
}

// ---------------------------------------------------------------------------
// Kernel 2: coefficients. One CTA per batch element (32 CTAs, 256 threads).
//   h = relu(pooled @ w1^T + b1)
//   delta = tanh(z/2) == 2*sigmoid(z) - 1
//   a[k,c] = (k==0) + 1.0*delta(z_alpha);  q[k,c] = (k==0) + 0.5*delta(z_beta)
// ---------------------------------------------------------------------------
__global__ __launch_bounds__(256) void coef_kernel(const float* __restrict__ w1,
                                                   const float* __restrict__ b1,
                                                   const float* __restrict__ w2,
                                                   const float* __restrict__ b2) {
    const int b = blockIdx.x;
    const int t = threadIdx.x;

    __shared__ float sp[C];    // pooled row
    __shared__ float sh[HID];  // hidden

    sp[t] = g_pooled[b * C + t];
    __syncthreads();

    if (t < HID) {
        float acc = b1[t];
        const float* __restrict__ w1r = w1 + t * C;
#pragma unroll 8
        for (int i = 0; i < C; ++i) acc = fmaf(sp[i], w1r[i], acc);
        sh[t] = fmaxf(acc, 0.f);
    }
    __syncthreads();

    // thread t -> channel t: 4 dot products of length HID
    const int cc = t;
    float z00 = b2[2 * cc];               // k=0 alpha
    float z01 = b2[2 * cc + 1];           // k=0 beta
    float z10 = b2[512 + 2 * cc];         // k=1 alpha
    float z11 = b2[512 + 2 * cc + 1];     // k=1 beta
    const float* __restrict__ r00 = w2 + (size_t)(2 * cc) * HID;
    const float* __restrict__ r01 = w2 + (size_t)(2 * cc + 1) * HID;
    const float* __restrict__ r10 = w2 + (size_t)(512 + 2 * cc) * HID;
    const float* __restrict__ r11 = w2 + (size_t)(512 + 2 * cc + 1) * HID;
#pragma unroll
    for (int h = 0; h < HID; ++h) {
        const float hv = sh[h];
        z00 = fmaf(hv, r00[h], z00);
        z01 = fmaf(hv, r01[h], z01);
        z10 = fmaf(hv, r10[h], z10);
        z11 = fmaf(hv, r11[h], z11);
    }
    float4 cf;
    cf.x = 1.0f + tanhf(0.5f * z00);          // a0 = 1 + 1.0*delta
    cf.y =        tanhf(0.5f * z10);          // a1 = 0 + 1.0*delta
    cf.z = 1.0f + 0.5f * tanhf(0.5f * z01);   // q0 = 1 + 0.5*delta
    cf.w =        0.5f * tanhf(0.5f * z11);   // q1 = 0 + 0.5*delta
    g_coef[b * C + cc] = cf;
}

// ---------------------------------------------------------------------------
// Kernel 3: out = max(x*a0+q0, x*a1+q1). One plane per CTA, 256 threads,
// 4 front-batched float4 loads (MLP=4), reverse plane order, __ldcs reads
// (single-use), __stcs evict-first stores. Best-measured configuration.
// ---------------------------------------------------------------------------
__global__ __launch_bounds__(256) void apply_kernel(const float* __restrict__ x,
                                                    float* __restrict__ out) {
    const int p = (NPLANES - 1) - blockIdx.x;   // reverse traversal
    const int t = threadIdx.x;

    const float4 cf = __ldcg(&g_coef[p]);
    const float a0 = cf.x, a1 = cf.y, q0 = cf.z, q1 = cf.w;

    const float4* __restrict__ x4 = reinterpret_cast<const float4*>(x) + (size_t)p * (HW / 4);
    float4* __restrict__ o4       = reinterpret_cast<float4*>(out)     + (size_t)p * (HW / 4);

    // Front-batched loads
    float4 v0 = __ldcs(&x4[t]);
    float4 v1 = __ldcs(&x4[t + 256]);
    float4 v2 = __ldcs(&x4[t + 512]);
    float4 v3 = __ldcs(&x4[t + 768]);

    float4 r0, r1, r2, r3;
    r0.x = fmaxf(fmaf(v0.x, a0, q0), fmaf(v0.x, a1, q1));
    r0.y = fmaxf(fmaf(v0.y, a0, q0), fmaf(v0.y, a1, q1));
    r0.z = fmaxf(fmaf(v0.z, a0, q0), fmaf(v0.z, a1, q1));
    r0.w = fmaxf(fmaf(v0.w, a0, q0), fmaf(v0.w, a1, q1));
    r1.x = fmaxf(fmaf(v1.x, a0, q0), fmaf(v1.x, a1, q1));
    r1.y = fmaxf(fmaf(v1.y, a0, q0), fmaf(v1.y, a1, q1));
    r1.z = fmaxf(fmaf(v1.z, a0, q0), fmaf(v1.z, a1, q1));
    r1.w = fmaxf(fmaf(v1.w, a0, q0), fmaf(v1.w, a1, q1));
    r2.x = fmaxf(fmaf(v2.x, a0, q0), fmaf(v2.x, a1, q1));
    r2.y = fmaxf(fmaf(v2.y, a0, q0), fmaf(v2.y, a1, q1));
    r2.z = fmaxf(fmaf(v2.z, a0, q0), fmaf(v2.z, a1, q1));
    r2.w = fmaxf(fmaf(v2.w, a0, q0), fmaf(v2.w, a1, q1));
    r3.x = fmaxf(fmaf(v3.x, a0, q0), fmaf(v3.x, a1, q1));
    r3.y = fmaxf(fmaf(v3.y, a0, q0), fmaf(v3.y, a1, q1));
    r3.z = fmaxf(fmaf(v3.z, a0, q0), fmaf(v3.z, a1, q1));
    r3.w = fmaxf(fmaf(v3.w, a0, q0), fmaf(v3.w, a1, q1));

    __stcs(&o4[t],       r0);
    __stcs(&o4[t + 256], r1);
    __stcs(&o4[t + 512], r2);
    __stcs(&o4[t + 768], r3);
}

extern "C" void kernel_launch(void* const* d_in, const int* in_sizes, int n_in,
                              void* d_out, int out_size) {
    const float* x  = (const float*)d_in[0];
    const float* w1 = (const float*)d_in[1];
    const float* b1 = (const float*)d_in[2];
    const float* w2 = (const float*)d_in[3];
    const float* b2 = (const float*)d_in[4];
    float* out = (float*)d_out;

    pool_kernel <<<NPLANES, 256>>>(x);
    coef_kernel <<<BS,      256>>>(w1, b1, w2, b2);
    apply_kernel<<<NPLANES, 256>>>(x, out);
}